// round 6
// baseline (speedup 1.0000x reference)
#include <cuda_runtime.h>
#include <cstdint>

// KV-cache scatter-copy via copy-engine path.
//   L=8, B=2, H=8, S_FULL=4096, S_NEW=4, D=128, fp32
// out (2,L,B,H,S_FULL,D):
//   slab0 = past_k, slab1 = past_v  -> two contiguous 256MB D2D memcpys
//   then overlay the (L,B,H,S_NEW,D) windows from new_k/new_v at
//   target_positions[b] (512KB total, ~3us kernel).
//
// R6 probe: does cudaMemcpyAsync D2D (copy engines) beat the ~85%-of-spec
// SM LDG/STG wall? Harness explicitly allows D2D memcpyAsync under capture.

static constexpr unsigned D4      = 32;        // float4 per row
static constexpr unsigned S_FULL  = 4096;
static constexpr unsigned S_NEW   = 4;
static constexpr unsigned H       = 8;
static constexpr unsigned B       = 2;
static constexpr unsigned L       = 8;
static constexpr size_t   PAST_F4 = (size_t)L * B * H * S_FULL * D4;  // 2^24
// overlay: 2 * L*B*H*S_NEW*D4 float4 = 32768
static constexpr unsigned OVL_F4  = 2u * L * B * H * S_NEW * D4;      // 32768

__global__ void __launch_bounds__(256) kv_overlay_kernel(
    const float4* __restrict__ nk,
    const float4* __restrict__ nv,
    const int*    __restrict__ tpos,
    float4*       __restrict__ out)
{
    const unsigned i = blockIdx.x * 256u + threadIdx.x;   // < OVL_F4 = 2^15

    // i = ((((kv*L + l)*B + b)*H + h)*S_NEW + sn)*D4 + d4
    const unsigned d4 = i & (D4 - 1);
    const unsigned sn = (i >> 5) & (S_NEW - 1);
    const unsigned h  = (i >> 7) & (H - 1);
    const unsigned b  = (i >> 10) & (B - 1);
    const unsigned l  = (i >> 11) & (L - 1);
    const unsigned kv = i >> 14;

    const unsigned off = (unsigned)__ldg(&tpos[b]);

    // source: new tensors share the same (l,b,h,sn,d4) packing as i's low bits
    const unsigned src = i & ((OVL_F4 / 2u) - 1u);
    const float4 val = kv ? __ldg(&nv[src]) : __ldg(&nk[src]);

    // dest: (kv,l,b,h, off+sn, d4) in (2,L,B,H,S_FULL,D)
    const size_t dst = ((((( (size_t)kv * L + l) * B + b) * H + h) * S_FULL)
                        + off + sn) * D4 + d4;
    out[dst] = val;
}

extern "C" void kernel_launch(void* const* d_in, const int* in_sizes, int n_in,
                              void* d_out, int out_size)
{
    const float4* pk = (const float4*)d_in[0];
    const float4* pv = (const float4*)d_in[1];
    const float4* nk = (const float4*)d_in[2];
    const float4* nv = (const float4*)d_in[3];
    const int*    tp = (const int*)d_in[4];
    float4*       out = (float4*)d_out;

    const size_t slab_bytes = PAST_F4 * sizeof(float4);   // 256 MB

    // Bulk copies (legacy stream; serialize with the overlay below).
    cudaMemcpyAsync(out,           pk, slab_bytes, cudaMemcpyDeviceToDevice, 0);
    cudaMemcpyAsync(out + PAST_F4, pv, slab_bytes, cudaMemcpyDeviceToDevice, 0);

    // Overlay the new-token windows (must run after the copies).
    kv_overlay_kernel<<<OVL_F4 / 256, 256>>>(nk, nv, tp, out);
}

// round 7
// speedup vs baseline: 1.0454x; 1.0454x over previous
#include <cuda_runtime.h>
#include <cstdint>

// FINAL: KV-cache scatter-copy, pure HBM streaming at the read/write-turnaround
// wall (~85% of 8TB/s; confirmed invariant across MLP 1-8, 128/256-bit access,
// occ 50-83%, tile 1-64KB, cache policies, and the CE-memcpy path).
//   L=8, B=2, H=8, S_FULL=4096, S_NEW=4, D=128, fp32
// out (2,L,B,H,S_FULL,D) = stack(past_k, past_v) with a 4-row window per
// (l,b,h) overwritten from new_k/new_v at target_positions[b].
//
// Best variant (R3): 8x float4 per thread, front-batched loads (MLP_p1=8),
// streaming .cs loads on the read-once past data, .cs stores, block-uniform
// kv/l/b/h decode (tile = 2^11 float4 < 2^17 boundary).

static constexpr unsigned D4       = 32;                       // float4 per row
static constexpr unsigned S_FULL   = 4096;
static constexpr unsigned S_NEW    = 4;
static constexpr unsigned H        = 8;
static constexpr unsigned B        = 2;
static constexpr unsigned L        = 8;
static constexpr unsigned PAST_F4  = L * B * H * S_FULL * D4;  // 2^24
static constexpr unsigned TOTAL_F4 = 2u * PAST_F4;             // 2^25

static constexpr unsigned TPB  = 256;
static constexpr unsigned U    = 8;
static constexpr unsigned TILE = TPB * U;                      // 2048 float4 per block

__global__ void __launch_bounds__(TPB) kv_scatter_copy_final(
    const float4* __restrict__ pk,
    const float4* __restrict__ pv,
    const float4* __restrict__ nk,
    const float4* __restrict__ nv,
    const int*    __restrict__ tpos,
    float4*       __restrict__ out)
{
    const unsigned base = blockIdx.x * TILE + threadIdx.x;

    // Bits >= 17 (h|b|l|kv) are uniform across the whole block.
    const unsigned r  = base >> 17;
    const unsigned h  = r & (H - 1);
    const unsigned b  = (r >> 3) & (B - 1);
    const unsigned l  = (r >> 4) & (L - 1);
    const unsigned kv = r >> 7;

    const unsigned off = (unsigned)__ldg(&tpos[b]);

    const float4* __restrict__ past = kv ? pv : pk;     // same layout as out slab
    const float4* __restrict__ nw   = (kv ? nv : nk)
                                      + (((l * B + b) * H + h) * S_NEW) * D4;

    float4 v[U];
#pragma unroll
    for (unsigned u = 0; u < U; u++) {
        const unsigned i  = base + u * TPB;
        const unsigned s  = (i >> 5) & (S_FULL - 1);
        const unsigned d4 = i & (D4 - 1);
        const unsigned w  = s - off;                    // in-window iff < S_NEW (unsigned wrap)
        if (w < S_NEW) {
            v[u] = __ldg(nw + w * D4 + d4);             // tiny window: keep in L2
        } else {
            v[u] = __ldcs(past + (i & (PAST_F4 - 1)));  // read-once bulk: streaming
        }
    }
#pragma unroll
    for (unsigned u = 0; u < U; u++) {
        __stcs(&out[base + u * TPB], v[u]);             // streaming store
    }
}

extern "C" void kernel_launch(void* const* d_in, const int* in_sizes, int n_in,
                              void* d_out, int out_size)
{
    const float4* pk = (const float4*)d_in[0];
    const float4* pv = (const float4*)d_in[1];
    const float4* nk = (const float4*)d_in[2];
    const float4* nv = (const float4*)d_in[3];
    const int*    tp = (const int*)d_in[4];
    float4*       out = (float4*)d_out;

    constexpr unsigned blocks = TOTAL_F4 / TILE;        // 16384
    kv_scatter_copy_final<<<blocks, TPB>>>(pk, pv, nk, nv, tp, out);
}